// round 15
// baseline (speedup 1.0000x reference)
#include <cuda_runtime.h>

#define W    512
#define CH   8            // rows per chunk
#define NCH  64           // chunks per column
#define CPB  8            // columns per block
#define TPB  512          // CPB * NCH
#define NBLK 64           // 512 / CPB  (each block does BOTH images)
#define BIG  4096

__device__ double   g_sum[NBLK][4];   // [block][imgFG, imgBG, tgtFG, tgtBG]
__device__ unsigned g_cnt[NBLK][4];
__device__ unsigned g_ctr;

struct Carry { int cfg, cbg, ufg, ubg; };

__device__ __forceinline__ void pixel_pass(unsigned bbits, unsigned mbits,
                                           const Carry& c, const float* lut,
                                           float& sfg, float& sbg,
                                           unsigned& nfg, unsigned& nbg) {
    const unsigned Z = (~bbits) & 0xFFu;
    float s0 = 0.0f, s1 = 0.0f, t0 = 0.0f, t1 = 0.0f;
#pragma unroll
    for (int j = 0; j < CH; j++) {
        bool     bb    = (bbits >> j) & 1u;
        unsigned opp   = bb ? Z : bbits;
        unsigned below = opp & ((1u << j) - 1u);
        unsigned above = opp & (0xFFFFFFFFu << (j + 1));
        int dn = below ? (j - 31 + __clz(below)) : BIG;
        int up = above ? (__ffs(above) - 1 - j)  : BIG;
        int fc = (bb ? c.cfg : c.cbg) + j + 1;
        int bc = (bb ? c.ufg : c.ubg) + (CH - j);
        int idx = min(min(min(dn, up), min(fc, bc)), 1024);
        float d  = lut[idx];
        bool  mm = (mbits >> j) & 1u;
        float afg = (mm &&  bb) ? d : 0.0f;
        float abg = (mm && !bb) ? d : 0.0f;
        if (j & 1) { s1 += afg; t1 += abg; }
        else       { s0 += afg; t0 += abg; }
    }
    sfg = s0 + s1;  sbg = t0 + t1;
    nfg = __popc(mbits & bbits);
    nbg = __popc(mbits & Z);
}

__global__ __launch_bounds__(TPB) void morph_all(const float* __restrict__ img,
                                                 const float* __restrict__ mask,
                                                 const float* __restrict__ tgt,
                                                 float* __restrict__ out) {
    __shared__ float    lut[1025];
    __shared__ unsigned LpI[TPB], MpI[TPB], LpT[TPB], MpT[TPB];
    __shared__ double   wsum[16][4];
    __shared__ unsigned wcnt[16][4];
    __shared__ int      isLast;
    __shared__ double   fsum[4];
    __shared__ unsigned fcnt[4];

    const int tid   = threadIdx.x;
    const int b     = blockIdx.x;
    const int cloc  = tid & (CPB - 1);
    const int chunk = tid >> 3;                // 0..63
    const int col   = b * CPB + cloc;
    const size_t base = (size_t)(chunk * CH) * W + col;

    // ---- 24 batched loads (mask read ONCE for both images) ----
    float vi[CH], vt[CH], vm[CH];
#pragma unroll
    for (int j = 0; j < CH; j++) {
        vi[j] = img [base + j * W];
        vt[j] = tgt [base + j * W];
        vm[j] = mask[base + j * W];
    }
    unsigned bI = 0u, bT = 0u, mbits = 0u;
#pragma unroll
    for (int j = 0; j < CH; j++) {
        bI    |= (vi[j] > 0.22f) ? (1u << j) : 0u;
        bT    |= (vt[j] > 0.22f) ? (1u << j) : 0u;
        mbits |= (vm[j] > 0.5f)  ? (1u << j) : 0u;
    }
    const unsigned ZI = (~bI) & 0xFFu, ZT = (~bT) & 0xFFu;

    // chunk-boundary distances, O(1) bit ops
    int LfgI = ZI ? (__clz(ZI) - 24) : 1024,  LbgI = bI ? (__clz(bI) - 24) : 1024;
    int MfgI = ZI ? (__ffs(ZI) - 1)  : 1024,  MbgI = bI ? (__ffs(bI) - 1)  : 1024;
    int LfgT = ZT ? (__clz(ZT) - 24) : 1024,  LbgT = bT ? (__clz(bT) - 24) : 1024;
    int MfgT = ZT ? (__ffs(ZT) - 1)  : 1024,  MbgT = bT ? (__ffs(bT) - 1)  : 1024;
    LpI[tid] = ((unsigned)LfgI << 16) | (unsigned)LbgI;
    MpI[tid] = ((unsigned)MfgI << 16) | (unsigned)MbgI;
    LpT[tid] = ((unsigned)LfgT << 16) | (unsigned)LbgT;
    MpT[tid] = ((unsigned)MfgT << 16) | (unsigned)MbgT;

    for (int v = tid; v < 1025; v += TPB)
        lut[v] = (v == 1024) ? 1024.0f
                             : __fsqrt_rn((float)(v * v + (v & 1)) * 0.5f);
    __syncthreads();

    // ---- carries (nearest-first, early-exit), both images ----
    Carry cI = {1024, 1024, 1024, 1024}, cT = {1024, 1024, 1024, 1024};
    for (int m = chunk - 1; m >= 0; m--) {
        int off = CH * (chunk - 1 - m);
        bool needI = (off < cI.cfg) | (off < cI.cbg);
        bool needT = (off < cT.cfg) | (off < cT.cbg);
        if (!(needI | needT)) break;
        int s = m * CPB + cloc;
        unsigned LI = LpI[s], LT = LpT[s];
        cI.cfg = min(cI.cfg, (int)(LI >> 16) + off);
        cI.cbg = min(cI.cbg, (int)(LI & 0xFFFFu) + off);
        cT.cfg = min(cT.cfg, (int)(LT >> 16) + off);
        cT.cbg = min(cT.cbg, (int)(LT & 0xFFFFu) + off);
    }
    cI.cfg = min(cI.cfg, 1024); cI.cbg = min(cI.cbg, 1024);
    cT.cfg = min(cT.cfg, 1024); cT.cbg = min(cT.cbg, 1024);
    for (int m = chunk + 1; m < NCH; m++) {
        int off = CH * (m - chunk - 1);
        bool needI = (off < cI.ufg) | (off < cI.ubg);
        bool needT = (off < cT.ufg) | (off < cT.ubg);
        if (!(needI | needT)) break;
        int s = m * CPB + cloc;
        unsigned MI = MpI[s], MT = MpT[s];
        cI.ufg = min(cI.ufg, (int)(MI >> 16) + off);
        cI.ubg = min(cI.ubg, (int)(MI & 0xFFFFu) + off);
        cT.ufg = min(cT.ufg, (int)(MT >> 16) + off);
        cT.ubg = min(cT.ubg, (int)(MT & 0xFFFFu) + off);
    }
    cI.ufg = min(cI.ufg, 1024); cI.ubg = min(cI.ubg, 1024);
    cT.ufg = min(cT.ufg, 1024); cT.ubg = min(cT.ubg, 1024);

    // ---- per-pixel passes, both images ----
    float    sI, tI, sT, tT;
    unsigned nI, oI, nT, oT;
    pixel_pass(bI, mbits, cI, lut, sI, tI, nI, oI);
    pixel_pass(bT, mbits, cT, lut, sT, tT, nT, oT);

    // ---- warp shfl reduction (fixed order) ----
#pragma unroll
    for (int o = 16; o > 0; o >>= 1) {
        sI += __shfl_down_sync(0xFFFFFFFFu, sI, o);
        tI += __shfl_down_sync(0xFFFFFFFFu, tI, o);
        sT += __shfl_down_sync(0xFFFFFFFFu, sT, o);
        tT += __shfl_down_sync(0xFFFFFFFFu, tT, o);
        nI += __shfl_down_sync(0xFFFFFFFFu, nI, o);
        oI += __shfl_down_sync(0xFFFFFFFFu, oI, o);
        nT += __shfl_down_sync(0xFFFFFFFFu, nT, o);
        oT += __shfl_down_sync(0xFFFFFFFFu, oT, o);
    }
    const int wid = tid >> 5;
    if ((tid & 31) == 0) {
        wsum[wid][0] = (double)sI;  wsum[wid][1] = (double)tI;
        wsum[wid][2] = (double)sT;  wsum[wid][3] = (double)tT;
        wcnt[wid][0] = nI;  wcnt[wid][1] = oI;
        wcnt[wid][2] = nT;  wcnt[wid][3] = oT;
    }
    __syncthreads();
    if (tid < 16) {
        double   a0 = wsum[tid][0], a1 = wsum[tid][1];
        double   a2 = wsum[tid][2], a3 = wsum[tid][3];
        unsigned c0 = wcnt[tid][0], c1 = wcnt[tid][1];
        unsigned c2 = wcnt[tid][2], c3 = wcnt[tid][3];
#pragma unroll
        for (int o = 8; o > 0; o >>= 1) {
            a0 += __shfl_down_sync(0xFFFFu, a0, o);
            a1 += __shfl_down_sync(0xFFFFu, a1, o);
            a2 += __shfl_down_sync(0xFFFFu, a2, o);
            a3 += __shfl_down_sync(0xFFFFu, a3, o);
            c0 += __shfl_down_sync(0xFFFFu, c0, o);
            c1 += __shfl_down_sync(0xFFFFu, c1, o);
            c2 += __shfl_down_sync(0xFFFFu, c2, o);
            c3 += __shfl_down_sync(0xFFFFu, c3, o);
        }
        if (tid == 0) {
            g_sum[b][0] = a0; g_sum[b][1] = a1; g_sum[b][2] = a2; g_sum[b][3] = a3;
            g_cnt[b][0] = c0; g_cnt[b][1] = c1; g_cnt[b][2] = c2; g_cnt[b][3] = c3;
            __threadfence();
            isLast = (atomicAdd(&g_ctr, 1u) == NBLK - 1);
        }
    }
    __syncthreads();

    // ---- last block: parallel deterministic final reduction + loss ----
    if (isLast) {
        if (tid < 128) {
            int ph = tid >> 5, ln = tid & 31;   // 4 phases x 32 lanes
            double   s = 0.0;
            unsigned c = 0u;
#pragma unroll
            for (int t = 0; t < 2; t++) {
                int k = ln + 32 * t;
                s += g_sum[k][ph];
                c += g_cnt[k][ph];
            }
#pragma unroll
            for (int o = 16; o > 0; o >>= 1) {
                s += __shfl_down_sync(0xFFFFFFFFu, s, o);
                c += __shfl_down_sync(0xFFFFFFFFu, c, o);
            }
            if (ln == 0) { fsum[ph] = s; fcnt[ph] = c; }
        }
        __syncthreads();
        if (tid == 0) {
            const double VX2   = 21.0;          // 2 * VOXEL_SIZE
            const double TH_MU = 48.7578, TH_SD = 5.2874;
            const double SP_MU = 156.729, SP_SD = 46.1809;
            double n0 = fcnt[0] ? (double)fcnt[0] : 1.0;
            double n1 = fcnt[1] ? (double)fcnt[1] : 1.0;
            double n2 = fcnt[2] ? (double)fcnt[2] : 1.0;
            double n3 = fcnt[3] ? (double)fcnt[3] : 1.0;
            double tl = VX2 * fsum[0] / n0;     // thickness  (img)
            double sl = VX2 * fsum[1] / n1;     // separation (img)
            double th = VX2 * fsum[2] / n2;     // thickness  (tgt)
            double sh = VX2 * fsum[3] / n3;     // separation (tgt)
            double l1 = (tl - TH_MU) / TH_SD - (th - TH_MU) / TH_SD;
            double l7 = (sl - SP_MU) / SP_SD - (sh - SP_MU) / SP_SD;
            out[0] = (float)(0.5 * (l1 * l1 + l7 * l7));
            g_ctr = 0;                          // reset for next graph replay
        }
    }
}

extern "C" void kernel_launch(void* const* d_in, const int* in_sizes, int n_in,
                              void* d_out, int out_size) {
    const float* img  = (const float*)d_in[0];
    const float* mask = (const float*)d_in[1];
    const float* tgt  = (const float*)d_in[2];
    morph_all<<<NBLK, TPB>>>(img, mask, tgt, (float*)d_out);
}

// round 16
// speedup vs baseline: 1.1597x; 1.1597x over previous
#include <cuda_runtime.h>

#define W    512
#define CH   16           // rows per chunk
#define NCH  32           // chunks per column
#define CPB  8            // columns per block
#define TPB  256          // CPB * NCH
#define NBLK 128          // 2 images * (512 / CPB)
#define BIG  4096

__device__ double   g_sum[NBLK][2];   // [block][0=fg/thickness, 1=bg/separation]
__device__ unsigned g_cnt[NBLK];      // packed: fg | bg<<16  (<=4096 each, fits)
__device__ unsigned g_ctr;

__global__ __launch_bounds__(TPB) void morph_all(const float* __restrict__ img,
                                                 const float* __restrict__ mask,
                                                 const float* __restrict__ tgt,
                                                 float* __restrict__ out) {
    __shared__ unsigned Lpack[TPB];     // fwd dists at chunk's last row
    __shared__ unsigned Mpack[TPB];     // local bwd dists at chunk's row 0
    __shared__ double   wsum[8][2];
    __shared__ unsigned wcnt[8];
    __shared__ int      isLast;
    __shared__ double   fsum[4];
    __shared__ unsigned fcnt[4];

    const int tid   = threadIdx.x;
    const int b     = blockIdx.x;
    const int im    = b >> 6;                  // 0 = img, 1 = target
    const int cloc  = tid & (CPB - 1);
    const int chunk = tid >> 3;                // 0..31
    const int col   = ((b & 63) * CPB) + cloc;
    const int rowBase = chunk * CH;

    const float* ps = (im ? tgt : img) + (size_t)rowBase * W + col;
    const float* pm = mask              + (size_t)rowBase * W + col;

    // ---- loads -> bitmasks (batched LDGs, high MLP) ----
    unsigned bbits = 0u, mbits = 0u;
#pragma unroll
    for (int j = 0; j < CH; j++) {
        bbits |= (ps[j * W] > 0.22f) ? (1u << j) : 0u;
        mbits |= (pm[j * W] > 0.5f)  ? (1u << j) : 0u;
    }
    const unsigned Z = (~bbits) & 0xFFFFu;

    // chunk-boundary distances, O(1) bit ops
    int Lfg = Z     ? (__clz(Z)     - 16) : 1024;  // fwd fg-dist at last row
    int Lbg = bbits ? (__clz(bbits) - 16) : 1024;  // fwd bg-dist at last row
    int Mfg = Z     ? (__ffs(Z)     - 1)  : 1024;  // bwd fg-dist at row 0
    int Mbg = bbits ? (__ffs(bbits) - 1)  : 1024;  // bwd bg-dist at row 0
    Lpack[tid] = ((unsigned)Lfg << 16) | (unsigned)Lbg;
    Mpack[tid] = ((unsigned)Mfg << 16) | (unsigned)Mbg;
    __syncthreads();

    // ---- carries across chunks (nearest-first, early-exit) ----
    int cfg = 1024, cbg = 1024;                // exact fwd dist at row rowBase-1
    for (int m = chunk - 1; m >= 0; m--) {
        int off = CH * (chunk - 1 - m);
        if (off >= cfg && off >= cbg) break;
        unsigned Lp = Lpack[m * CPB + cloc];
        cfg = min(cfg, (int)(Lp >> 16) + off);
        cbg = min(cbg, (int)(Lp & 0xFFFFu) + off);
    }
    int ufg = 1024, ubg = 1024;                // exact bwd dist at row rowBase+CH
    for (int m = chunk + 1; m < NCH; m++) {
        int off = CH * (m - chunk - 1);
        if (off >= ufg && off >= ubg) break;
        unsigned Mp = Mpack[m * CPB + cloc];
        ufg = min(ufg, (int)(Mp >> 16) + off);
        ubg = min(ubg, (int)(Mp & 0xFFFFu) + off);
    }

    // ---- per-pixel distances: independent bit math + direct approx sqrt ----
    float s0 = 0.0f, s1 = 0.0f, t0 = 0.0f, t1 = 0.0f;
#pragma unroll
    for (int j = 0; j < CH; j++) {
        bool     bb    = (bbits >> j) & 1u;
        unsigned opp   = bb ? Z : bbits;
        unsigned below = opp & ((1u << j) - 1u);
        unsigned above = opp & (0xFFFFFFFFu << (j + 1));
        int dn = below ? (j - 31 + __clz(below)) : BIG;   // nearest opp below
        int up = above ? (__ffs(above) - 1 - j)  : BIG;   // nearest opp above
        int fc = (bb ? cfg : cbg) + j + 1;                // via chunk start
        int bc = (bb ? ufg : ubg) + (CH - j);             // via chunk end
        int idx = min(min(dn, up), min(fc, bc));
        // d(idx) = sqrt((idx^2 + (idx&1)) / 2); uniform-column (idx>1023) -> 1024
        float x = (float)(idx * idx + (idx & 1)) * 0.5f;
        float d;
        asm("sqrt.approx.f32 %0, %1;" : "=f"(d) : "f"(x));
        d = (idx > 1023) ? 1024.0f : d;
        bool  mm  = (mbits >> j) & 1u;
        float afg = (mm &&  bb) ? d : 0.0f;
        float abg = (mm && !bb) ? d : 0.0f;
        if (j & 1) { s1 += afg; t1 += abg; }
        else       { s0 += afg; t0 += abg; }
    }
    float    sfg = s0 + s1, sbg = t0 + t1;
    unsigned cnt = __popc(mbits & bbits) | (__popc(mbits & Z) << 16);

    // ---- warp shfl reduction (3 quantities; fixed order) ----
#pragma unroll
    for (int o = 16; o > 0; o >>= 1) {
        sfg += __shfl_down_sync(0xFFFFFFFFu, sfg, o);
        sbg += __shfl_down_sync(0xFFFFFFFFu, sbg, o);
        cnt += __shfl_down_sync(0xFFFFFFFFu, cnt, o);
    }
    const int wid = tid >> 5;
    if ((tid & 31) == 0) {
        wsum[wid][0] = (double)sfg;  wsum[wid][1] = (double)sbg;
        wcnt[wid] = cnt;
    }
    __syncthreads();
    if (tid < 8) {
        double   a0 = wsum[tid][0], a1 = wsum[tid][1];
        unsigned c  = wcnt[tid];
#pragma unroll
        for (int o = 4; o > 0; o >>= 1) {
            a0 += __shfl_down_sync(0xFFu, a0, o);
            a1 += __shfl_down_sync(0xFFu, a1, o);
            c  += __shfl_down_sync(0xFFu, c,  o);
        }
        if (tid == 0) {
            g_sum[b][0] = a0;  g_sum[b][1] = a1;
            g_cnt[b] = c;                      // fg<=4096, bg<=4096: no overflow
            __threadfence();
            isLast = (atomicAdd(&g_ctr, 1u) == NBLK - 1);
        }
    }
    __syncthreads();

    // ---- last block: parallel deterministic final reduction + loss ----
    if (isLast) {
        if (tid < 128) {
            int ph = tid >> 5, ln = tid & 31;   // 4 phases x 32 lanes
            int base = (ph >> 1) * 64;          // blocks of that image
            int e    = ph & 1;
            double   s = 0.0;
            unsigned c = 0u;
#pragma unroll
            for (int t = 0; t < 2; t++) {
                int k = base + ln + 32 * t;
                s += g_sum[k][e];
                unsigned pk = g_cnt[k];
                c += e ? (pk >> 16) : (pk & 0xFFFFu);
            }
#pragma unroll
            for (int o = 16; o > 0; o >>= 1) {
                s += __shfl_down_sync(0xFFFFFFFFu, s, o);
                c += __shfl_down_sync(0xFFFFFFFFu, c, o);
            }
            if (ln == 0) { fsum[ph] = s; fcnt[ph] = c; }
        }
        __syncthreads();
        if (tid == 0) {
            const double VX2   = 21.0;          // 2 * VOXEL_SIZE
            const double TH_MU = 48.7578, TH_SD = 5.2874;
            const double SP_MU = 156.729, SP_SD = 46.1809;
            double n0 = fcnt[0] ? (double)fcnt[0] : 1.0;
            double n1 = fcnt[1] ? (double)fcnt[1] : 1.0;
            double n2 = fcnt[2] ? (double)fcnt[2] : 1.0;
            double n3 = fcnt[3] ? (double)fcnt[3] : 1.0;
            double tl = VX2 * fsum[0] / n0;     // thickness  (img)
            double sl = VX2 * fsum[1] / n1;     // separation (img)
            double th = VX2 * fsum[2] / n2;     // thickness  (tgt)
            double sh = VX2 * fsum[3] / n3;     // separation (tgt)
            double l1 = (tl - TH_MU) / TH_SD - (th - TH_MU) / TH_SD;
            double l7 = (sl - SP_MU) / SP_SD - (sh - SP_MU) / SP_SD;
            out[0] = (float)(0.5 * (l1 * l1 + l7 * l7));
            g_ctr = 0;                          // reset for next graph replay
        }
    }
}

extern "C" void kernel_launch(void* const* d_in, const int* in_sizes, int n_in,
                              void* d_out, int out_size) {
    const float* img  = (const float*)d_in[0];
    const float* mask = (const float*)d_in[1];
    const float* tgt  = (const float*)d_in[2];
    morph_all<<<NBLK, TPB>>>(img, mask, tgt, (float*)d_out);
}

// round 17
// speedup vs baseline: 1.1800x; 1.0175x over previous
#include <cuda_runtime.h>

#define W    512
#define CH   16           // rows per chunk
#define NCH  32           // chunks per column
#define CPB  8            // columns per block
#define TPB  256          // CPB * NCH
#define NBLK 128          // 2 images * (512 / CPB)
#define BIG  4096

__device__ double   g_sum[NBLK][2];   // [block][0=fg/thickness, 1=bg/separation]
__device__ unsigned g_cnt[NBLK];      // packed: fg | bg<<16
__device__ unsigned g_ctr;

__global__ __launch_bounds__(TPB) void morph_all(const float* __restrict__ img,
                                                 const float* __restrict__ mask,
                                                 const float* __restrict__ tgt,
                                                 float* __restrict__ out) {
    __shared__ float    lut[1025];
    __shared__ unsigned Lpack[TPB];     // fwd dists at chunk's last row
    __shared__ unsigned Mpack[TPB];     // local bwd dists at chunk's row 0
    __shared__ double   wsum[8][2];
    __shared__ unsigned wcnt[8];
    __shared__ int      isLast;
    __shared__ double   fsum[4];
    __shared__ unsigned fcnt[4];

    const int tid   = threadIdx.x;
    const int b     = blockIdx.x;
    const int im    = b >> 6;                  // 0 = img, 1 = target
    const int cloc  = tid & (CPB - 1);
    const int chunk = tid >> 3;                // 0..31
    const int col   = ((b & 63) * CPB) + cloc;
    const int rowBase = chunk * CH;

    const float* ps = (im ? tgt : img) + (size_t)rowBase * W + col;
    const float* pm = mask              + (size_t)rowBase * W + col;

    // ---- loads -> bitmasks (batched LDGs, high MLP) ----
    unsigned bbits = 0u, mbits = 0u;
#pragma unroll
    for (int j = 0; j < CH; j++) {
        bbits |= (ps[j * W] > 0.22f) ? (1u << j) : 0u;
        mbits |= (pm[j * W] > 0.5f)  ? (1u << j) : 0u;
    }
    const unsigned Z = (~bbits) & 0xFFFFu;

    // chunk-boundary distances, O(1) bit ops
    int Lfg = Z     ? (__clz(Z)     - 16) : 1024;  // fwd fg-dist at last row
    int Lbg = bbits ? (__clz(bbits) - 16) : 1024;  // fwd bg-dist at last row
    int Mfg = Z     ? (__ffs(Z)     - 1)  : 1024;  // bwd fg-dist at row 0
    int Mbg = bbits ? (__ffs(bbits) - 1)  : 1024;  // bwd bg-dist at row 0
    Lpack[tid] = ((unsigned)Lfg << 16) | (unsigned)Lbg;
    Mpack[tid] = ((unsigned)Mfg << 16) | (unsigned)Mbg;

    for (int v = tid; v < 1025; v += TPB)
        lut[v] = (v == 1024) ? 1024.0f
                             : __fsqrt_rn((float)(v * v + (v & 1)) * 0.5f);
    __syncthreads();

    // ---- carries across chunks (nearest-first, early-exit) ----
    int cfg = 1024, cbg = 1024;                // exact fwd dist at row rowBase-1
    for (int m = chunk - 1; m >= 0; m--) {
        int off = CH * (chunk - 1 - m);
        if (off >= cfg && off >= cbg) break;
        unsigned Lp = Lpack[m * CPB + cloc];
        cfg = min(cfg, (int)(Lp >> 16) + off);
        cbg = min(cbg, (int)(Lp & 0xFFFFu) + off);
    }
    int ufg = 1024, ubg = 1024;                // exact bwd dist at row rowBase+CH
    for (int m = chunk + 1; m < NCH; m++) {
        int off = CH * (m - chunk - 1);
        if (off >= ufg && off >= ubg) break;
        unsigned Mp = Mpack[m * CPB + cloc];
        ufg = min(ufg, (int)(Mp >> 16) + off);
        ubg = min(ubg, (int)(Mp & 0xFFFFu) + off);
    }

    // ---- per-pixel distances: independent bit math, LUT lookup ----
    float s0 = 0.0f, s1 = 0.0f, t0 = 0.0f, t1 = 0.0f;
#pragma unroll
    for (int j = 0; j < CH; j++) {
        bool     bb    = (bbits >> j) & 1u;
        unsigned opp   = bb ? Z : bbits;
        unsigned below = opp & ((1u << j) - 1u);
        unsigned above = opp & (0xFFFFFFFFu << (j + 1));
        int dn = below ? (j - 31 + __clz(below)) : BIG;   // nearest opp below
        int up = above ? (__ffs(above) - 1 - j)  : BIG;   // nearest opp above
        int fc = (bb ? cfg : cbg) + j + 1;                // via chunk start
        int bc = (bb ? ufg : ubg) + (CH - j);             // via chunk end
        int idx = min(min(min(dn, up), min(fc, bc)), 1024);
        float d  = lut[idx];
        bool  mm = (mbits >> j) & 1u;
        float afg = (mm &&  bb) ? d : 0.0f;
        float abg = (mm && !bb) ? d : 0.0f;
        if (j & 1) { s1 += afg; t1 += abg; }
        else       { s0 += afg; t0 += abg; }
    }
    float    sfg = s0 + s1, sbg = t0 + t1;
    unsigned cnt = __popc(mbits & bbits) | (__popc(mbits & Z) << 16);

    // ---- warp shfl reduction (3 quantities; fixed order -> deterministic) ----
#pragma unroll
    for (int o = 16; o > 0; o >>= 1) {
        sfg += __shfl_down_sync(0xFFFFFFFFu, sfg, o);
        sbg += __shfl_down_sync(0xFFFFFFFFu, sbg, o);
        cnt += __shfl_down_sync(0xFFFFFFFFu, cnt, o);
    }
    const int wid = tid >> 5;
    if ((tid & 31) == 0) {
        wsum[wid][0] = (double)sfg;  wsum[wid][1] = (double)sbg;
        wcnt[wid] = cnt;
    }
    __syncthreads();
    if (tid < 8) {
        double   a0 = wsum[tid][0], a1 = wsum[tid][1];
        unsigned c  = wcnt[tid];
#pragma unroll
        for (int o = 4; o > 0; o >>= 1) {
            a0 += __shfl_down_sync(0xFFu, a0, o);
            a1 += __shfl_down_sync(0xFFu, a1, o);
            c  += __shfl_down_sync(0xFFu, c,  o);
        }
        if (tid == 0) {
            g_sum[b][0] = a0;  g_sum[b][1] = a1;
            g_cnt[b] = c;                      // fg<=4096, bg<=4096: no overflow
            __threadfence();
            isLast = (atomicAdd(&g_ctr, 1u) == NBLK - 1);
        }
    }
    __syncthreads();

    // ---- last block: parallel deterministic final reduction + loss ----
    if (isLast) {
        if (tid < 128) {
            int ph = tid >> 5, ln = tid & 31;   // 4 phases x 32 lanes
            int base = (ph >> 1) * 64;          // blocks of that image
            int e    = ph & 1;
            double   s = 0.0;
            unsigned c = 0u;
#pragma unroll
            for (int t = 0; t < 2; t++) {
                int k = base + ln + 32 * t;
                s += g_sum[k][e];
                unsigned pk = g_cnt[k];
                c += e ? (pk >> 16) : (pk & 0xFFFFu);
            }
#pragma unroll
            for (int o = 16; o > 0; o >>= 1) {
                s += __shfl_down_sync(0xFFFFFFFFu, s, o);
                c += __shfl_down_sync(0xFFFFFFFFu, c, o);
            }
            if (ln == 0) { fsum[ph] = s; fcnt[ph] = c; }
        }
        __syncthreads();
        if (tid == 0) {
            const double VX2   = 21.0;          // 2 * VOXEL_SIZE
            const double TH_MU = 48.7578, TH_SD = 5.2874;
            const double SP_MU = 156.729, SP_SD = 46.1809;
            double n0 = fcnt[0] ? (double)fcnt[0] : 1.0;
            double n1 = fcnt[1] ? (double)fcnt[1] : 1.0;
            double n2 = fcnt[2] ? (double)fcnt[2] : 1.0;
            double n3 = fcnt[3] ? (double)fcnt[3] : 1.0;
            double tl = VX2 * fsum[0] / n0;     // thickness  (img)
            double sl = VX2 * fsum[1] / n1;     // separation (img)
            double th = VX2 * fsum[2] / n2;     // thickness  (tgt)
            double sh = VX2 * fsum[3] / n3;     // separation (tgt)
            double l1 = (tl - TH_MU) / TH_SD - (th - TH_MU) / TH_SD;
            double l7 = (sl - SP_MU) / SP_SD - (sh - SP_MU) / SP_SD;
            out[0] = (float)(0.5 * (l1 * l1 + l7 * l7));
            g_ctr = 0;                          // reset for next graph replay
        }
    }
}

extern "C" void kernel_launch(void* const* d_in, const int* in_sizes, int n_in,
                              void* d_out, int out_size) {
    const float* img  = (const float*)d_in[0];
    const float* mask = (const float*)d_in[1];
    const float* tgt  = (const float*)d_in[2];
    morph_all<<<NBLK, TPB>>>(img, mask, tgt, (float*)d_out);
}